// round 13
// baseline (speedup 1.0000x reference)
#include <cuda_runtime.h>
#include <cuda_bf16.h>
#include <math.h>
#include <stdint.h>

#define BB 8
#define NN 384
#define DD 512
#define BN (BB * NN)   // 3072
#define SMROW 80       // smem bytes per 32-bf16 row (64B data + 16B pad)

// phase block counts
#define PREP_N   1408
#define PROJ_N   384
#define SCORES_N 288
#define FIN_N    384
#define B0_PROJ   (PREP_N)
#define B0_SCORES (B0_PROJ + PROJ_N)
#define B0_FIN    (B0_SCORES + SCORES_N)
#define TOTAL_B   (B0_FIN + FIN_N)

// ---------------- device scratch ----------------
__device__ __nv_bfloat16 g_hh[BN * DD];                   // h hi
__device__ __nv_bfloat16 g_wqh[DD * DD], g_wql[DD * DD];  // Wq pair
__device__ __nv_bfloat16 g_wkh[DD * DD], g_wkl[DD * DD];  // Wk pair
__device__ __nv_bfloat16 g_qh[BN * DD];                   // q hi only
__device__ __nv_bfloat16 g_kh[BN * DD], g_kl[BN * DD];    // k pair
__device__ float g_left[BN], g_right[BN];
__device__ float g_raw[(size_t)BB * NN * NN];

// phase counters (zero-init; reset by last finalize block each run)
__device__ unsigned g_cnt_prep, g_cnt_proj, g_cnt_scores, g_cnt_fin;

// ---------------- helpers ----------------
__device__ __forceinline__ uint32_t smem_u32(const void* p) {
    uint32_t a;
    asm("{ .reg .u64 t; cvta.to.shared.u64 t, %1; cvt.u32.u64 %0, t; }"
        : "=r"(a) : "l"(p));
    return a;
}

__device__ __forceinline__ void cp16(uint32_t dst, const void* src) {
    asm volatile("cp.async.cg.shared.global [%0], [%1], 16;"
                 :: "r"(dst), "l"(src) : "memory");
}
#define CP_COMMIT() asm volatile("cp.async.commit_group;" ::: "memory")

__device__ __forceinline__ void ldsm4(uint32_t* r, uint32_t addr) {
    asm volatile("ldmatrix.sync.aligned.m8n8.x4.shared.b16 {%0,%1,%2,%3}, [%4];"
                 : "=r"(r[0]), "=r"(r[1]), "=r"(r[2]), "=r"(r[3]) : "r"(addr));
}

__device__ __forceinline__ void mma16816(float* c, const uint32_t* a, const uint32_t* b) {
    asm volatile(
        "mma.sync.aligned.m16n8k16.row.col.f32.bf16.bf16.f32 "
        "{%0,%1,%2,%3}, {%4,%5,%6,%7}, {%8,%9}, {%0,%1,%2,%3};"
        : "+f"(c[0]), "+f"(c[1]), "+f"(c[2]), "+f"(c[3])
        : "r"(a[0]), "r"(a[1]), "r"(a[2]), "r"(a[3]), "r"(b[0]), "r"(b[1]));
}

__device__ __forceinline__ void split_store2(
    __nv_bfloat16* oh, __nv_bfloat16* ol, size_t idx, float v0, float v1)
{
    __nv_bfloat16 h0 = __float2bfloat16(v0);
    __nv_bfloat16 h1 = __float2bfloat16(v1);
    __nv_bfloat162 hp; hp.x = h0; hp.y = h1;
    *(__nv_bfloat162*)(oh + idx) = hp;
    __nv_bfloat162 lp;
    lp.x = __float2bfloat16(v0 - __bfloat162float(h0));
    lp.y = __float2bfloat16(v1 - __bfloat162float(h1));
    *(__nv_bfloat162*)(ol + idx) = lp;
}

// producer: flush this block's writes, then bump the phase counter once.
__device__ __forceinline__ void phase_arrive(unsigned* cnt) {
    __threadfence();
    __syncthreads();
    if (threadIdx.x == 0) atomicAdd(cnt, 1u);
}

// consumer: wait for a phase to fully complete.
__device__ __forceinline__ void phase_gate(unsigned* cnt, unsigned target) {
    if (threadIdx.x == 0) {
        volatile unsigned* p = cnt;
        while (*p < target) __nanosleep(128);
    }
    __syncthreads();
    __threadfence();
}

// ---------------------------------------------------------------------------
// 2-term split GEMM core: C += Ah * (Bh + Bl)^T.
// Tile M = MW*MF*16, N = NW*NF*8, K = 512 in 16 chunks of 32.
// Stage layout: Ah | Bh | Bl.
// ---------------------------------------------------------------------------
template<int MW, int NW, int MF, int NF, int STAGES>
__device__ __forceinline__ void gemm2(
    const __nv_bfloat16* __restrict__ Ah,
    const __nv_bfloat16* __restrict__ Bh, const __nv_bfloat16* __restrict__ Bl,
    char* smem, float acc[MF][NF][4])
{
    constexpr int MT = MW * MF * 16;
    constexpr int NT = NW * NF * 8;
    constexpr int A_BYTES = MT * SMROW;
    constexpr int B_BYTES = NT * SMROW;
    constexpr int STAGE = A_BYTES + 2 * B_BYTES;
    constexpr int NTHR = MW * NW * 32;

    const int tid = threadIdx.x;
    const int wid = tid >> 5, lane = tid & 31;
    const int wm = wid % MW, wn = wid / MW;
    const uint32_t s0 = smem_u32(smem);

    const uint32_t a_off = (uint32_t)(lane & 15) * SMROW + (uint32_t)(lane >> 4) * 16;
    const uint32_t b_off = (uint32_t)((lane & 7) + ((lane >> 4) << 3)) * SMROW
                         + (uint32_t)((lane >> 3) & 1) * 16;

    auto issue = [&](int cc) {
        const int k0 = cc * 32;
        const uint32_t sb = s0 + (cc % STAGES) * STAGE;
#pragma unroll
        for (int idx = tid; idx < MT * 4; idx += NTHR) {
            const int r = idx >> 2, g = idx & 3;
            cp16(sb + (uint32_t)r * SMROW + g * 16,
                 Ah + (size_t)r * DD + k0 + g * 8);
        }
#pragma unroll
        for (int idx = tid; idx < NT * 4; idx += NTHR) {
            const int r = idx >> 2, g = idx & 3;
            const uint32_t so = (uint32_t)r * SMROW + g * 16;
            const size_t go = (size_t)r * DD + k0 + g * 8;
            cp16(sb + A_BYTES + so, Bh + go);
            cp16(sb + A_BYTES + B_BYTES + so, Bl + go);
        }
        CP_COMMIT();
    };

#pragma unroll
    for (int p = 0; p < STAGES - 1; p++) issue(p);

#pragma unroll 1
    for (int c = 0; c < 16; c++) {
        if (c + STAGES - 1 < 16) issue(c + STAGES - 1);

        const int rem = 15 - c;
        const int ahead = rem < (STAGES - 1) ? rem : (STAGES - 1);
        if      (ahead <= 0) asm volatile("cp.async.wait_group 0;" ::: "memory");
        else if (ahead == 1) asm volatile("cp.async.wait_group 1;" ::: "memory");
        else if (ahead == 2) asm volatile("cp.async.wait_group 2;" ::: "memory");
        else                 asm volatile("cp.async.wait_group 3;" ::: "memory");
        __syncthreads();

        const uint32_t sb = s0 + (c % STAGES) * STAGE;
#pragma unroll
        for (int ks = 0; ks < 2; ks++) {
            const uint32_t kb = ks * 32;
            uint32_t ahf[MF][4];
#pragma unroll
            for (int mf = 0; mf < MF; mf++) {
                const uint32_t rb = (uint32_t)(wm * MF * 16 + mf * 16) * SMROW + kb + a_off;
                ldsm4(ahf[mf], sb + rb);
            }
#pragma unroll
            for (int np = 0; np < NF / 2; np++) {
                const uint32_t nb = (uint32_t)(wn * NF * 8 + np * 16) * SMROW + kb + b_off;
                uint32_t bh[4], bl[4];
                ldsm4(bh, sb + A_BYTES + nb);
                ldsm4(bl, sb + A_BYTES + B_BYTES + nb);
#pragma unroll
                for (int mf = 0; mf < MF; mf++) {
                    mma16816(acc[mf][np * 2],     ahf[mf], bh);
                    mma16816(acc[mf][np * 2 + 1], ahf[mf], bh + 2);
                    mma16816(acc[mf][np * 2],     ahf[mf], bl);
                    mma16816(acc[mf][np * 2 + 1], ahf[mf], bl + 2);
                }
            }
        }
        __syncthreads();
    }
}

// ---------------------------------------------------------------------------
// Phase bodies
// ---------------------------------------------------------------------------
__device__ void do_prep(int blk,
    const float* __restrict__ h,
    const float* __restrict__ Wq, const float* __restrict__ Wk,
    const float* __restrict__ wlr, const float* __restrict__ blr,
    const float* __restrict__ wrl, const float* __restrict__ brl)
{
    if (blk < 768) {
        const long o = (long)blk * 2048 + (long)threadIdx.x * 8;
        float4 x0 = *(const float4*)(h + o);
        float4 x1 = *(const float4*)(h + o + 4);
        float v[8] = {x0.x, x0.y, x0.z, x0.w, x1.x, x1.y, x1.z, x1.w};
#pragma unroll
        for (int e = 0; e < 8; e += 2) {
            __nv_bfloat162 hp;
            hp.x = __float2bfloat16(v[e]);
            hp.y = __float2bfloat16(v[e + 1]);
            *(__nv_bfloat162*)(g_hh + o + e) = hp;
        }
    } else if (blk < 1024) {
        const float* src;
        __nv_bfloat16 *dh, *dl;
        long base;
        if (blk < 896) { src = Wq; dh = g_wqh; dl = g_wql; base = (long)(blk - 768) * 2048; }
        else           { src = Wk; dh = g_wkh; dl = g_wkl; base = (long)(blk - 896) * 2048; }

        const long o = base + (long)threadIdx.x * 8;
        float4 x0 = *(const float4*)(src + o);
        float4 x1 = *(const float4*)(src + o + 4);
        float v[8] = {x0.x, x0.y, x0.z, x0.w, x1.x, x1.y, x1.z, x1.w};
#pragma unroll
        for (int e = 0; e < 8; e++) {
            __nv_bfloat16 hi = __float2bfloat16(v[e]);
            dh[o + e] = hi;
            dl[o + e] = __float2bfloat16(v[e] - __bfloat162float(hi));
        }
    } else {
        const int row = (blk - 1024) * 8 + (threadIdx.x >> 5);
        const int lane = threadIdx.x & 31;
        const float* hr = h + (size_t)row * DD;
        float sl = 0.f, sr = 0.f;
        for (int d = lane; d < DD; d += 32) {
            float hv = hr[d];
            sl = fmaf(hv, wlr[d], sl);
            sr = fmaf(hv, wrl[d], sr);
        }
#pragma unroll
        for (int o = 16; o; o >>= 1) {
            sl += __shfl_down_sync(0xFFFFFFFFu, sl, o);
            sr += __shfl_down_sync(0xFFFFFFFFu, sr, o);
        }
        if (lane == 0) {
            g_left[row]  = sl + blr[0];
            g_right[row] = sr + brl[0];
        }
    }
}

__device__ void do_proj(int t, char* smem, const float* __restrict__ bq)
{
    const int z    = t / 192;
    const int rest = t - z * 192;
    const int m0 = (rest >> 3) * 128;
    const int n0 = (rest & 7) * 64;

    const __nv_bfloat16* Bh = (z ? g_wkh : g_wqh) + (size_t)n0 * DD;
    const __nv_bfloat16* Bl = (z ? g_wkl : g_wql) + (size_t)n0 * DD;

    float acc[2][4][4];
#pragma unroll
    for (int a = 0; a < 2; a++)
#pragma unroll
        for (int f = 0; f < 4; f++)
#pragma unroll
            for (int e = 0; e < 4; e++) acc[a][f][e] = 0.f;

    gemm2<4, 2, 2, 4, 3>(g_hh + (size_t)m0 * DD, Bh, Bl, smem, acc);

    const int wid = threadIdx.x >> 5, lane = threadIdx.x & 31;
    const int wm = wid & 3, wn = wid >> 2;

#pragma unroll
    for (int mf = 0; mf < 2; mf++) {
        const int r0 = m0 + wm * 32 + mf * 16 + (lane >> 2);
#pragma unroll
        for (int f = 0; f < 4; f++) {
            const int c = n0 + wn * 32 + f * 8 + (lane & 3) * 2;
            if (z == 0) {
                const float b0 = __ldg(&bq[c]), b1 = __ldg(&bq[c + 1]);
                __nv_bfloat162 p0, p1;
                p0.x = __float2bfloat16(acc[mf][f][0] + b0);
                p0.y = __float2bfloat16(acc[mf][f][1] + b1);
                p1.x = __float2bfloat16(acc[mf][f][2] + b0);
                p1.y = __float2bfloat16(acc[mf][f][3] + b1);
                *(__nv_bfloat162*)(g_qh + (size_t)r0 * DD + c) = p0;
                *(__nv_bfloat162*)(g_qh + (size_t)(r0 + 8) * DD + c) = p1;
            } else {
                split_store2(g_kh, g_kl, (size_t)r0 * DD + c,
                             acc[mf][f][0], acc[mf][f][1]);
                split_store2(g_kh, g_kl, (size_t)(r0 + 8) * DD + c,
                             acc[mf][f][2], acc[mf][f][3]);
            }
        }
    }
}

__device__ void do_scores(int s, char* smem,
    const float* __restrict__ alpha_p,
    const float* __restrict__ beta_p,
    const float* __restrict__ gamma_p)
{
    const int b    = s / 36;
    const int rest = s - b * 36;
    const int m0 = (rest / 6) * 64;
    const int n0 = (rest % 6) * 64;
    const size_t abase = ((size_t)b * NN + m0) * DD;
    const size_t bbase = ((size_t)b * NN + n0) * DD;

    float acc[2][2][4];
#pragma unroll
    for (int a = 0; a < 2; a++)
#pragma unroll
        for (int f = 0; f < 2; f++)
#pragma unroll
            for (int e = 0; e < 4; e++) acc[a][f][e] = 0.f;

    gemm2<2, 4, 2, 2, 4>(g_qh + abase, g_kh + bbase, g_kl + bbase, smem, acc);

    const float alpha = alpha_p[0], beta = beta_p[0], gamma = gamma_p[0];
    const int wid = threadIdx.x >> 5, lane = threadIdx.x & 31;
    const int wm = wid & 1, wn = wid >> 1;

#pragma unroll
    for (int mf = 0; mf < 2; mf++) {
        const int rl = m0 + wm * 32 + mf * 16 + (lane >> 2);
#pragma unroll
        for (int rr = 0; rr < 2; rr++) {
            const int i = rl + rr * 8;
            const float lft = g_left[b * NN + i];
            const float rgt = g_right[b * NN + i];
            float* rb = g_raw + ((size_t)b * NN + i) * NN;
#pragma unroll
            for (int f = 0; f < 2; f++) {
                const int j = n0 + wn * 16 + f * 8 + (lane & 3) * 2;
                float2 o;
                {
                    const float dv = (j >= i) ? lft : rgt;
                    float raw = fmaf(alpha, acc[mf][f][rr * 2],
                                     fmaf(beta, dv, gamma));
                    o.x = fminf(fmaxf(raw, -16.f), 14.f);
                }
                {
                    const float dv = (j + 1 >= i) ? lft : rgt;
                    float raw = fmaf(alpha, acc[mf][f][rr * 2 + 1],
                                     fmaf(beta, dv, gamma));
                    o.y = fminf(fmaxf(raw, -16.f), 14.f);
                }
                *(float2*)(rb + j) = o;
            }
        }
    }
}

__device__ void do_finalize(int fb, char* smem,
    const float* __restrict__ mask,
    float* __restrict__ r_out,
    float* __restrict__ am_out)
{
    const int wid = threadIdx.x >> 5;
    const int lane = threadIdx.x & 31;
    const int bi = fb * 8 + wid;          // 8 rows per block, 384 blocks
    const int b = bi / NN;
    const int i = bi - b * NN;

    float* Srow = (float*)smem + wid * (NN + 1);

    const float* rawp = g_raw + (size_t)bi * NN + lane * 12;
    float raw[12];
    *(float4*)(raw + 0) = *(const float4*)(rawp + 0);
    *(float4*)(raw + 4) = *(const float4*)(rawp + 4);
    *(float4*)(raw + 8) = *(const float4*)(rawp + 8);

    float l1[12], pre[12];
    float run = 0.f;
#pragma unroll
    for (int e = 0; e < 12; e++) {
        l1[e] = -__logf(1.f + __expf(raw[e]));
        run += l1[e];
        pre[e] = run;
    }

    float x = run;
#pragma unroll
    for (int o = 1; o < 32; o <<= 1) {
        float y = __shfl_up_sync(0xFFFFFFFFu, x, o);
        if (lane >= o) x += y;
    }
    const float base = x - run;

    if (lane == 0) Srow[0] = 0.f;
#pragma unroll
    for (int e = 0; e < 12; e++)
        Srow[lane * 12 + e + 1] = base + pre[e];
    __syncwarp();

    const float mi = mask[b * NN + i];
    float mj[12];
    {
        const float* mp = mask + b * NN + lane * 12;
        *(float4*)(mj + 0) = *(const float4*)(mp + 0);
        *(float4*)(mj + 4) = *(const float4*)(mp + 4);
        *(float4*)(mj + 8) = *(const float4*)(mp + 8);
    }

    float r[12], am[12];
#pragma unroll
    for (int e = 0; e < 12; e++) {
        const int j = lane * 12 + e;
        const float lp = raw[e] + l1[e];
        float a;
        if (i == j) {
            a = lp - 10000.f;
        } else if (i < j) {
            const int lo = max(2 * i - j + 1, 0);
            a = lp + (Srow[j] - Srow[i + 1]) + (Srow[i] - Srow[lo]);
        } else {
            const int hi = min(2 * i - j, NN - 1);
            a = lp + (Srow[i] - Srow[j + 1]) + (Srow[hi + 1] - Srow[i + 1]);
        }
        r[e] = a;
        am[e] = mi * mj[e];
    }

    float* rp = r_out + (size_t)bi * NN + lane * 12;
    *(float4*)(rp + 0) = *(float4*)(r + 0);
    *(float4*)(rp + 4) = *(float4*)(r + 4);
    *(float4*)(rp + 8) = *(float4*)(r + 8);
    if (am_out) {
        float* ap = am_out + (size_t)bi * NN + lane * 12;
        *(float4*)(ap + 0) = *(float4*)(am + 0);
        *(float4*)(ap + 4) = *(float4*)(am + 4);
        *(float4*)(ap + 8) = *(float4*)(am + 8);
    }
}

// ---------------------------------------------------------------------------
// Fused pipeline: one launch, phase gates via device counters.
// Deadlock-free: CTAs dispatch in bid order; consumers only ever wait on
// strictly earlier bid ranges, and producers never wait on later phases.
// ---------------------------------------------------------------------------
__global__ void __launch_bounds__(256) fused_kernel(
    const float* __restrict__ h,    const float* __restrict__ mask,
    const float* __restrict__ Wq,   const float* __restrict__ bq,
    const float* __restrict__ Wk,
    const float* __restrict__ wlr,  const float* __restrict__ blr,
    const float* __restrict__ wrl,  const float* __restrict__ brl,
    const float* __restrict__ alpha, const float* __restrict__ beta,
    const float* __restrict__ gamma,
    float* __restrict__ r_out, float* __restrict__ am_out)
{
    extern __shared__ char smem[];
    const int bid = blockIdx.x;

    if (bid < B0_PROJ) {
        do_prep(bid, h, Wq, Wk, wlr, blr, wrl, brl);
        phase_arrive(&g_cnt_prep);
    } else if (bid < B0_SCORES) {
        phase_gate(&g_cnt_prep, PREP_N);
        do_proj(bid - B0_PROJ, smem, bq);
        phase_arrive(&g_cnt_proj);
    } else if (bid < B0_FIN) {
        phase_gate(&g_cnt_proj, PROJ_N);
        do_scores(bid - B0_SCORES, smem, alpha, beta, gamma);
        phase_arrive(&g_cnt_scores);
    } else {
        phase_gate(&g_cnt_scores, SCORES_N);
        do_finalize(bid - B0_FIN, smem, mask, r_out, am_out);
        // arrive + last-block counter reset (replay safety)
        __threadfence();
        __syncthreads();
        if (threadIdx.x == 0) {
            const unsigned v = atomicAdd(&g_cnt_fin, 1u);
            if (v == FIN_N - 1) {
                g_cnt_prep = 0; g_cnt_proj = 0;
                g_cnt_scores = 0; g_cnt_fin = 0;
                __threadfence();
            }
        }
    }
}

// ---------------------------------------------------------------------------
// Launch
// ---------------------------------------------------------------------------
extern "C" void kernel_launch(void* const* d_in, const int* in_sizes, int n_in,
                              void* d_out, int out_size)
{
    const float* h     = (const float*)d_in[0];
    const float* mask  = (const float*)d_in[1];
    const float* Wq    = (const float*)d_in[2];
    const float* bq    = (const float*)d_in[3];
    const float* Wk    = (const float*)d_in[4];
    const float* wlr   = (const float*)d_in[5];
    const float* blr   = (const float*)d_in[6];
    const float* wrl   = (const float*)d_in[7];
    const float* brl   = (const float*)d_in[8];
    const float* alpha = (const float*)d_in[9];
    const float* beta  = (const float*)d_in[10];
    const float* gamma = (const float*)d_in[11];

    float* r_out = (float*)d_out;
    const long long BNN = (long long)BB * NN * NN;
    float* am_out = (out_size >= 2 * BNN) ? (r_out + BNN) : nullptr;

    // smem: max(proj 3*20480, scores 4*15360, finalize 8*(NN+1)*4) = 61440
    static bool attr_set = false;
    const int smem_bytes = 61440;
    if (!attr_set) {
        cudaFuncSetAttribute(fused_kernel,
                             cudaFuncAttributeMaxDynamicSharedMemorySize, smem_bytes);
        attr_set = true;
    }

    fused_kernel<<<TOTAL_B, 256, smem_bytes>>>(
        h, mask, Wq, bq, Wk, wlr, blr, wrl, brl,
        alpha, beta, gamma, r_out, am_out);
}

// round 14
// speedup vs baseline: 1.1038x; 1.1038x over previous
#include <cuda_runtime.h>
#include <cuda_bf16.h>
#include <math.h>
#include <stdint.h>

#define BB 8
#define NN 384
#define DD 512
#define BN (BB * NN)   // 3072
#define SMROW 80       // smem bytes per 32-bf16 row (64B data + 16B pad)

// gram smem layout
#define GRROW 144               // 64 bf16 row + 16B pad
#define GARR  (32 * GRROW)      // one 32x64 bf16 array: 4608 B

// ---------------- device scratch ----------------
__device__ __nv_bfloat16 g_hh[BN * DD], g_hl[BN * DD];    // h pair
__device__ __nv_bfloat16 g_Gth[DD * DD], g_Gtl[DD * DD];  // Gt[v][u] pair
__device__ __nv_bfloat16 g_ph[BN * DD];                   // P = h@G, hi only
__device__ float g_w2[DD];
__device__ float g_left[BN], g_right[BN], g_bias[BN];
__device__ float g_raw[(size_t)BB * NN * NN];

// ---------------- helpers ----------------
__device__ __forceinline__ uint32_t smem_u32(const void* p) {
    uint32_t a;
    asm("{ .reg .u64 t; cvta.to.shared.u64 t, %1; cvt.u32.u64 %0, t; }"
        : "=r"(a) : "l"(p));
    return a;
}

__device__ __forceinline__ void cp16(uint32_t dst, const void* src) {
    asm volatile("cp.async.cg.shared.global [%0], [%1], 16;"
                 :: "r"(dst), "l"(src) : "memory");
}
#define CP_COMMIT() asm volatile("cp.async.commit_group;" ::: "memory")

__device__ __forceinline__ void ldsm4(uint32_t* r, uint32_t addr) {
    asm volatile("ldmatrix.sync.aligned.m8n8.x4.shared.b16 {%0,%1,%2,%3}, [%4];"
                 : "=r"(r[0]), "=r"(r[1]), "=r"(r[2]), "=r"(r[3]) : "r"(addr));
}

__device__ __forceinline__ void ldsm4t(uint32_t* r, uint32_t addr) {
    asm volatile("ldmatrix.sync.aligned.m8n8.x4.trans.shared.b16 {%0,%1,%2,%3}, [%4];"
                 : "=r"(r[0]), "=r"(r[1]), "=r"(r[2]), "=r"(r[3]) : "r"(addr));
}

__device__ __forceinline__ void mma16816(float* c, const uint32_t* a, const uint32_t* b) {
    asm volatile(
        "mma.sync.aligned.m16n8k16.row.col.f32.bf16.bf16.f32 "
        "{%0,%1,%2,%3}, {%4,%5,%6,%7}, {%8,%9}, {%0,%1,%2,%3};"
        : "+f"(c[0]), "+f"(c[1]), "+f"(c[2]), "+f"(c[3])
        : "r"(a[0]), "r"(a[1]), "r"(a[2]), "r"(a[3]), "r"(b[0]), "r"(b[1]));
}

// ---------------------------------------------------------------------------
// prep: [0,64) gram (self-splitting, 2-term MMA); [64,66) w2; [66,450) lr;
// [450,1218) h pair split.
// ---------------------------------------------------------------------------
__global__ void __launch_bounds__(256) prep_kernel(
    const float* __restrict__ h,
    const float* __restrict__ Wq, const float* __restrict__ Wk,
    const float* __restrict__ bq,
    const float* __restrict__ wlr, const float* __restrict__ blr,
    const float* __restrict__ wrl, const float* __restrict__ brl)
{
    __shared__ char gs[2 * 64 * GRROW];   // 18432 B (mainloop uses 13824)
    const int blk = blockIdx.x;
    const int tid = threadIdx.x;

    if (blk < 64) {
        // Gt[v][u] = sum_m Wq[m][u] * Wk[m][v], tile 64x64.
        const int u0 = (blk & 7) * 64;
        const int v0 = (blk >> 3) * 64;
        const int wid = tid >> 5, lane = tid & 31;
        const int wm = wid & 3, wn = wid >> 2;
        const uint32_t s0 = smem_u32(gs);
        const int r = tid >> 3, c8 = (tid & 7) * 8;
        const int mat = lane >> 3, l7 = lane & 7;

        float acc[4][4];
#pragma unroll
        for (int f = 0; f < 4; f++)
#pragma unroll
            for (int e = 0; e < 4; e++) acc[f][e] = 0.f;

#pragma unroll 1
        for (int c = 0; c < 16; c++) {
            const int k0 = c * 32;
            // load fp32, convert inline: Wq -> hi only, Wk -> hi/lo
            {
                const float* qp = Wq + (size_t)(k0 + r) * DD + u0 + c8;
                const float* kp = Wk + (size_t)(k0 + r) * DD + v0 + c8;
                float4 q0 = *(const float4*)qp, q1 = *(const float4*)(qp + 4);
                float4 k0v = *(const float4*)kp, k1v = *(const float4*)(kp + 4);
                float qv[8] = {q0.x, q0.y, q0.z, q0.w, q1.x, q1.y, q1.z, q1.w};
                float kv[8] = {k0v.x, k0v.y, k0v.z, k0v.w, k1v.x, k1v.y, k1v.z, k1v.w};
                const uint32_t so = (uint32_t)r * GRROW + c8 * 2;
#pragma unroll
                for (int e = 0; e < 8; e += 2) {
                    __nv_bfloat162 qh2;
                    qh2.x = __float2bfloat16(qv[e]);
                    qh2.y = __float2bfloat16(qv[e + 1]);
                    *(__nv_bfloat162*)(gs + so + e * 2) = qh2;
                    __nv_bfloat16 kh0 = __float2bfloat16(kv[e]);
                    __nv_bfloat16 kh1 = __float2bfloat16(kv[e + 1]);
                    __nv_bfloat162 kh2; kh2.x = kh0; kh2.y = kh1;
                    *(__nv_bfloat162*)(gs + GARR + so + e * 2) = kh2;
                    __nv_bfloat162 kl2;
                    kl2.x = __float2bfloat16(kv[e] - __bfloat162float(kh0));
                    kl2.y = __float2bfloat16(kv[e + 1] - __bfloat162float(kh1));
                    *(__nv_bfloat162*)(gs + 2 * GARR + so + e * 2) = kl2;
                }
            }
            __syncthreads();
#pragma unroll
            for (int ks = 0; ks < 2; ks++) {
                uint32_t ah[4];
                const uint32_t ra = (uint32_t)(ks * 16 + (mat >> 1) * 8 + l7) * GRROW
                                  + (uint32_t)(wm * 32 + (mat & 1) * 16);
                ldsm4t(ah, s0 + ra);
#pragma unroll
                for (int np = 0; np < 2; np++) {
                    const uint32_t rb = (uint32_t)(ks * 16 + (mat & 1) * 8 + l7) * GRROW
                                      + (uint32_t)(wn * 32 + np * 16 + (mat >> 1) * 8) * 2;
                    uint32_t bh[4], bl[4];
                    ldsm4t(bh, s0 + GARR + rb);
                    ldsm4t(bl, s0 + 2 * GARR + rb);
                    mma16816(acc[np * 2],     ah, bh);
                    mma16816(acc[np * 2 + 1], ah, bh + 2);
                    mma16816(acc[np * 2],     ah, bl);
                    mma16816(acc[np * 2 + 1], ah, bl + 2);
                }
            }
            __syncthreads();
        }

        // epilogue: split + transpose via smem, coalesced store of Gt[v][u]
#pragma unroll
        for (int f = 0; f < 4; f++) {
#pragma unroll
            for (int e = 0; e < 4; e++) {
                const int u = wm * 16 + (lane >> 2) + (e >> 1) * 8;
                const int v = wn * 32 + f * 8 + (lane & 3) * 2 + (e & 1);
                const float val = acc[f][e];
                const __nv_bfloat16 hi = __float2bfloat16(val);
                *(__nv_bfloat16*)(gs + v * GRROW + u * 2) = hi;
                *(__nv_bfloat16*)(gs + 64 * GRROW + v * GRROW + u * 2) =
                    __float2bfloat16(val - __bfloat162float(hi));
            }
        }
        __syncthreads();
        for (int t = tid; t < 512; t += 256) {
            const int v = t >> 3, cc = t & 7;
            *(uint4*)(g_Gth + (size_t)(v0 + v) * DD + u0 + cc * 8) =
                *(uint4*)(gs + v * GRROW + cc * 16);
            *(uint4*)(g_Gtl + (size_t)(v0 + v) * DD + u0 + cc * 8) =
                *(uint4*)(gs + 64 * GRROW + v * GRROW + cc * 16);
        }
    } else if (blk < 66) {
        // w2[v] = sum_m bq[m] * Wk[m][v]
        const int v = (blk - 64) * 256 + tid;
        float s = 0.f;
#pragma unroll 8
        for (int m = 0; m < DD; m++)
            s = fmaf(__ldg(&bq[m]), __ldg(&Wk[(size_t)m * DD + v]), s);
        g_w2[v] = s;
    } else if (blk < 450) {
        const int row = (blk - 66) * 8 + (tid >> 5);
        const int lane = tid & 31;
        const float* hr = h + (size_t)row * DD;
        float sl = 0.f, sr = 0.f;
        for (int d = lane; d < DD; d += 32) {
            float hv = hr[d];
            sl = fmaf(hv, wlr[d], sl);
            sr = fmaf(hv, wrl[d], sr);
        }
#pragma unroll
        for (int o = 16; o; o >>= 1) {
            sl += __shfl_down_sync(0xFFFFFFFFu, sl, o);
            sr += __shfl_down_sync(0xFFFFFFFFu, sr, o);
        }
        if (lane == 0) {
            g_left[row]  = sl + blr[0];
            g_right[row] = sr + brl[0];
        }
    } else {
        const long o = (long)(blk - 450) * 2048 + (long)tid * 8;
        float4 x0 = *(const float4*)(h + o);
        float4 x1 = *(const float4*)(h + o + 4);
        float v[8] = {x0.x, x0.y, x0.z, x0.w, x1.x, x1.y, x1.z, x1.w};
#pragma unroll
        for (int e = 0; e < 8; e++) {
            __nv_bfloat16 hi = __float2bfloat16(v[e]);
            g_hh[o + e] = hi;
            g_hl[o + e] = __float2bfloat16(v[e] - __bfloat162float(hi));
        }
    }
}

// ---------------------------------------------------------------------------
// 2-term split GEMM core: C += Ah * (Bh + Bl)^T. A single array, B pair.
// Tile M = MW*MF*16, N = NW*NF*8, K = 512 in 16 chunks of 32.
// ---------------------------------------------------------------------------
template<int MW, int NW, int MF, int NF, int STAGES>
__device__ __forceinline__ void gemm2(
    const __nv_bfloat16* __restrict__ Ah,
    const __nv_bfloat16* __restrict__ Bh, const __nv_bfloat16* __restrict__ Bl,
    char* smem, float acc[MF][NF][4])
{
    constexpr int MT = MW * MF * 16;
    constexpr int NT = NW * NF * 8;
    constexpr int A_BYTES = MT * SMROW;
    constexpr int B_BYTES = NT * SMROW;
    constexpr int STAGE = A_BYTES + 2 * B_BYTES;
    constexpr int NTHR = MW * NW * 32;

    const int tid = threadIdx.x;
    const int wid = tid >> 5, lane = tid & 31;
    const int wm = wid % MW, wn = wid / MW;
    const uint32_t s0 = smem_u32(smem);

    const uint32_t a_off = (uint32_t)(lane & 15) * SMROW + (uint32_t)(lane >> 4) * 16;
    const uint32_t b_off = (uint32_t)((lane & 7) + ((lane >> 4) << 3)) * SMROW
                         + (uint32_t)((lane >> 3) & 1) * 16;

    auto issue = [&](int cc) {
        const int k0 = cc * 32;
        const uint32_t sb = s0 + (cc % STAGES) * STAGE;
#pragma unroll
        for (int idx = tid; idx < MT * 4; idx += NTHR) {
            const int r = idx >> 2, g = idx & 3;
            cp16(sb + (uint32_t)r * SMROW + g * 16,
                 Ah + (size_t)r * DD + k0 + g * 8);
        }
#pragma unroll
        for (int idx = tid; idx < NT * 4; idx += NTHR) {
            const int r = idx >> 2, g = idx & 3;
            const uint32_t so = (uint32_t)r * SMROW + g * 16;
            const size_t go = (size_t)r * DD + k0 + g * 8;
            cp16(sb + A_BYTES + so, Bh + go);
            cp16(sb + A_BYTES + B_BYTES + so, Bl + go);
        }
        CP_COMMIT();
    };

#pragma unroll
    for (int p = 0; p < STAGES - 1; p++) issue(p);

#pragma unroll 1
    for (int c = 0; c < 16; c++) {
        if (c + STAGES - 1 < 16) issue(c + STAGES - 1);

        const int rem = 15 - c;
        const int ahead = rem < (STAGES - 1) ? rem : (STAGES - 1);
        if      (ahead <= 0) asm volatile("cp.async.wait_group 0;" ::: "memory");
        else if (ahead == 1) asm volatile("cp.async.wait_group 1;" ::: "memory");
        else if (ahead == 2) asm volatile("cp.async.wait_group 2;" ::: "memory");
        else                 asm volatile("cp.async.wait_group 3;" ::: "memory");
        __syncthreads();

        const uint32_t sb = s0 + (c % STAGES) * STAGE;
#pragma unroll
        for (int ks = 0; ks < 2; ks++) {
            const uint32_t kb = ks * 32;
            uint32_t ahf[MF][4];
#pragma unroll
            for (int mf = 0; mf < MF; mf++) {
                const uint32_t rb = (uint32_t)(wm * MF * 16 + mf * 16) * SMROW + kb + a_off;
                ldsm4(ahf[mf], sb + rb);
            }
#pragma unroll
            for (int np = 0; np < NF / 2; np++) {
                const uint32_t nb = (uint32_t)(wn * NF * 8 + np * 16) * SMROW + kb + b_off;
                uint32_t bh[4], bl[4];
                ldsm4(bh, sb + A_BYTES + nb);
                ldsm4(bl, sb + A_BYTES + B_BYTES + nb);
#pragma unroll
                for (int mf = 0; mf < MF; mf++) {
                    mma16816(acc[mf][np * 2],     ahf[mf], bh);
                    mma16816(acc[mf][np * 2 + 1], ahf[mf], bh + 2);
                    mma16816(acc[mf][np * 2],     ahf[mf], bl);
                    mma16816(acc[mf][np * 2 + 1], ahf[mf], bl + 2);
                }
            }
        }
        __syncthreads();
    }
}

// ---------------------------------------------------------------------------
// mid: [0,192) P = h @ Gt^T tiles (128x64, 3-stage); [192,576) bias rows.
// ---------------------------------------------------------------------------
__global__ void __launch_bounds__(256) mid_kernel(const float* __restrict__ h)
{
    extern __shared__ char smem[];
    const int t = blockIdx.x;
    const int tid = threadIdx.x;

    if (t >= 192) {
        // bias_j = h_j . w2 (warp per row)
        const int row = (t - 192) * 8 + (tid >> 5);
        const int lane = tid & 31;
        const float* hr = h + (size_t)row * DD;
        float s = 0.f;
        for (int d = lane; d < DD; d += 32)
            s = fmaf(hr[d], g_w2[d], s);
#pragma unroll
        for (int o = 16; o; o >>= 1) s += __shfl_down_sync(0xFFFFFFFFu, s, o);
        if (lane == 0) g_bias[row] = s;
        return;
    }

    const int m0 = (t >> 3) * 128;
    const int n0 = (t & 7) * 64;

    float acc[2][4][4];
#pragma unroll
    for (int a = 0; a < 2; a++)
#pragma unroll
        for (int f = 0; f < 4; f++)
#pragma unroll
            for (int e = 0; e < 4; e++) acc[a][f][e] = 0.f;

    gemm2<4, 2, 2, 4, 3>(g_hh + (size_t)m0 * DD,
                         g_Gth + (size_t)n0 * DD, g_Gtl + (size_t)n0 * DD,
                         smem, acc);

    const int wid = tid >> 5, lane = tid & 31;
    const int wm = wid & 3, wn = wid >> 2;

#pragma unroll
    for (int mf = 0; mf < 2; mf++) {
        const int r0 = m0 + wm * 32 + mf * 16 + (lane >> 2);
#pragma unroll
        for (int f = 0; f < 4; f++) {
            const int c = n0 + wn * 32 + f * 8 + (lane & 3) * 2;
            __nv_bfloat162 p0, p1;
            p0.x = __float2bfloat16(acc[mf][f][0]);
            p0.y = __float2bfloat16(acc[mf][f][1]);
            p1.x = __float2bfloat16(acc[mf][f][2]);
            p1.y = __float2bfloat16(acc[mf][f][3]);
            *(__nv_bfloat162*)(g_ph + (size_t)r0 * DD + c) = p0;
            *(__nv_bfloat162*)(g_ph + (size_t)(r0 + 8) * DD + c) = p1;
        }
    }
}

// ---------------------------------------------------------------------------
// scores: per-batch S = P (hh+hl)^T + bias_j, tile 64x64, 4-stage.
// Grid (6,6,8) = 288 CTAs. raw = clip(alpha*(S+bias_j) + beta*d + gamma).
// ---------------------------------------------------------------------------
__global__ void __launch_bounds__(256) scores_kernel(
    const float* __restrict__ alpha_p,
    const float* __restrict__ beta_p,
    const float* __restrict__ gamma_p)
{
    extern __shared__ char smem[];
    const int b  = blockIdx.z;
    const int m0 = blockIdx.y * 64;
    const int n0 = blockIdx.x * 64;
    const size_t abase = ((size_t)b * NN + m0) * DD;
    const size_t bbase = ((size_t)b * NN + n0) * DD;

    float acc[2][2][4];
#pragma unroll
    for (int a = 0; a < 2; a++)
#pragma unroll
        for (int f = 0; f < 2; f++)
#pragma unroll
            for (int e = 0; e < 4; e++) acc[a][f][e] = 0.f;

    gemm2<2, 4, 2, 2, 4>(g_ph + abase, g_hh + bbase, g_hl + bbase, smem, acc);

    const float alpha = alpha_p[0], beta = beta_p[0], gamma = gamma_p[0];
    const int wid = threadIdx.x >> 5, lane = threadIdx.x & 31;
    const int wm = wid & 1, wn = wid >> 1;

#pragma unroll
    for (int mf = 0; mf < 2; mf++) {
        const int rl = m0 + wm * 32 + mf * 16 + (lane >> 2);
#pragma unroll
        for (int rr = 0; rr < 2; rr++) {
            const int i = rl + rr * 8;
            const float lft = g_left[b * NN + i];
            const float rgt = g_right[b * NN + i];
            float* rb = g_raw + ((size_t)b * NN + i) * NN;
#pragma unroll
            for (int f = 0; f < 2; f++) {
                const int j = n0 + wn * 16 + f * 8 + (lane & 3) * 2;
                float2 o;
                {
                    const float sc = acc[mf][f][rr * 2] + __ldg(&g_bias[b * NN + j]);
                    const float dv = (j >= i) ? lft : rgt;
                    float raw = fmaf(alpha, sc, fmaf(beta, dv, gamma));
                    o.x = fminf(fmaxf(raw, -16.f), 14.f);
                }
                {
                    const float sc = acc[mf][f][rr * 2 + 1] + __ldg(&g_bias[b * NN + j + 1]);
                    const float dv = (j + 1 >= i) ? lft : rgt;
                    float raw = fmaf(alpha, sc, fmaf(beta, dv, gamma));
                    o.y = fminf(fmaxf(raw, -16.f), 14.f);
                }
                *(float2*)(rb + j) = o;
            }
        }
    }
}

// ---------------------------------------------------------------------------
// finalize: warp-per-row, 4 rows per 128-thread block, 768 blocks.
// ---------------------------------------------------------------------------
__global__ void __launch_bounds__(128) finalize_kernel(
    const float* __restrict__ mask,
    float* __restrict__ r_out,
    float* __restrict__ am_out)
{
    const int wid = threadIdx.x >> 5;
    const int lane = threadIdx.x & 31;
    const int bi = blockIdx.x * 4 + wid;
    const int b = bi / NN;
    const int i = bi - b * NN;

    __shared__ float S[4][NN + 1];
    float* Srow = S[wid];

    const float* rawp = g_raw + (size_t)bi * NN + lane * 12;
    float raw[12];
    *(float4*)(raw + 0) = *(const float4*)(rawp + 0);
    *(float4*)(raw + 4) = *(const float4*)(rawp + 4);
    *(float4*)(raw + 8) = *(const float4*)(rawp + 8);

    float l1[12], pre[12];
    float run = 0.f;
#pragma unroll
    for (int e = 0; e < 12; e++) {
        l1[e] = -__logf(1.f + __expf(raw[e]));
        run += l1[e];
        pre[e] = run;
    }

    float x = run;
#pragma unroll
    for (int o = 1; o < 32; o <<= 1) {
        float y = __shfl_up_sync(0xFFFFFFFFu, x, o);
        if (lane >= o) x += y;
    }
    const float base = x - run;

    if (lane == 0) Srow[0] = 0.f;
#pragma unroll
    for (int e = 0; e < 12; e++)
        Srow[lane * 12 + e + 1] = base + pre[e];
    __syncwarp();

    const float mi = mask[b * NN + i];
    float mj[12];
    {
        const float* mp = mask + b * NN + lane * 12;
        *(float4*)(mj + 0) = *(const float4*)(mp + 0);
        *(float4*)(mj + 4) = *(const float4*)(mp + 4);
        *(float4*)(mj + 8) = *(const float4*)(mp + 8);
    }

    float r[12], am[12];
#pragma unroll
    for (int e = 0; e < 12; e++) {
        const int j = lane * 12 + e;
        const float lp = raw[e] + l1[e];
        float a;
        if (i == j) {
            a = lp - 10000.f;
        } else if (i < j) {
            const int lo = max(2 * i - j + 1, 0);
            a = lp + (Srow[j] - Srow[i + 1]) + (Srow[i] - Srow[lo]);
        } else {
            const int hi = min(2 * i - j, NN - 1);
            a = lp + (Srow[i] - Srow[j + 1]) + (Srow[hi + 1] - Srow[i + 1]);
        }
        r[e] = a;
        am[e] = mi * mj[e];
    }

    float* rp = r_out + (size_t)bi * NN + lane * 12;
    *(float4*)(rp + 0) = *(float4*)(r + 0);
    *(float4*)(rp + 4) = *(float4*)(r + 4);
    *(float4*)(rp + 8) = *(float4*)(r + 8);
    if (am_out) {
        float* ap = am_out + (size_t)bi * NN + lane * 12;
        *(float4*)(ap + 0) = *(float4*)(am + 0);
        *(float4*)(ap + 4) = *(float4*)(am + 4);
        *(float4*)(ap + 8) = *(float4*)(am + 8);
    }
}

// ---------------------------------------------------------------------------
// Launch
// ---------------------------------------------------------------------------
extern "C" void kernel_launch(void* const* d_in, const int* in_sizes, int n_in,
                              void* d_out, int out_size)
{
    const float* h     = (const float*)d_in[0];
    const float* mask  = (const float*)d_in[1];
    const float* Wq    = (const float*)d_in[2];
    const float* bq    = (const float*)d_in[3];
    const float* Wk    = (const float*)d_in[4];
    const float* wlr   = (const float*)d_in[5];
    const float* blr   = (const float*)d_in[6];
    const float* wrl   = (const float*)d_in[7];
    const float* brl   = (const float*)d_in[8];
    const float* alpha = (const float*)d_in[9];
    const float* beta  = (const float*)d_in[10];
    const float* gamma = (const float*)d_in[11];

    float* r_out = (float*)d_out;
    const long long BNN = (long long)BB * NN * NN;
    float* am_out = (out_size >= 2 * BNN) ? (r_out + BNN) : nullptr;

    // mid P-tiles: stage (128 + 2*64)*80 = 20480 B * 3 = 61440 B (3 CTAs/SM)
    // scores: stage (64 + 2*64)*80 = 15360 B * 4 = 61440 B (3 CTAs/SM)
    static bool attr_set = false;
    const int mid_smem = 61440, scores_smem = 61440;
    if (!attr_set) {
        cudaFuncSetAttribute(mid_kernel,
                             cudaFuncAttributeMaxDynamicSharedMemorySize, mid_smem);
        cudaFuncSetAttribute(scores_kernel,
                             cudaFuncAttributeMaxDynamicSharedMemorySize, scores_smem);
        attr_set = true;
    }

    prep_kernel<<<1218, 256>>>(h, Wq, Wk, bq, wlr, blr, wrl, brl);
    mid_kernel<<<576, 256, mid_smem>>>(h);
    scores_kernel<<<dim3(6, 6, 8), 256, scores_smem>>>(alpha, beta, gamma);
    finalize_kernel<<<768, 128>>>(mask, r_out, am_out);
}

// round 15
// speedup vs baseline: 1.6028x; 1.4521x over previous
#include <cuda_runtime.h>
#include <cuda_bf16.h>
#include <math.h>
#include <stdint.h>

#define BB 8
#define NN 384
#define DD 512
#define BN (BB * NN)   // 3072
#define SMROW 80       // smem bytes per 32-bf16 row (64B data + 16B pad)

// ---------------- device scratch ----------------
__device__ __nv_bfloat16 g_hh[BN * DD];                   // h bf16
__device__ __nv_bfloat16 g_wqh[DD * DD], g_wkh[DD * DD];  // W bf16
__device__ __nv_bfloat16 g_qh[BN * DD], g_kh[BN * DD];    // q, k bf16
__device__ float g_left[BN], g_right[BN];
__device__ float g_raw[(size_t)BB * NN * NN];

// ---------------- helpers ----------------
__device__ __forceinline__ uint32_t smem_u32(const void* p) {
    uint32_t a;
    asm("{ .reg .u64 t; cvta.to.shared.u64 t, %1; cvt.u32.u64 %0, t; }"
        : "=r"(a) : "l"(p));
    return a;
}

__device__ __forceinline__ void cp16(uint32_t dst, const void* src) {
    asm volatile("cp.async.cg.shared.global [%0], [%1], 16;"
                 :: "r"(dst), "l"(src) : "memory");
}
#define CP_COMMIT() asm volatile("cp.async.commit_group;" ::: "memory")

__device__ __forceinline__ void ldsm4(uint32_t* r, uint32_t addr) {
    asm volatile("ldmatrix.sync.aligned.m8n8.x4.shared.b16 {%0,%1,%2,%3}, [%4];"
                 : "=r"(r[0]), "=r"(r[1]), "=r"(r[2]), "=r"(r[3]) : "r"(addr));
}

__device__ __forceinline__ void mma16816(float* c, const uint32_t* a, const uint32_t* b) {
    asm volatile(
        "mma.sync.aligned.m16n8k16.row.col.f32.bf16.bf16.f32 "
        "{%0,%1,%2,%3}, {%4,%5,%6,%7}, {%8,%9}, {%0,%1,%2,%3};"
        : "+f"(c[0]), "+f"(c[1]), "+f"(c[2]), "+f"(c[3])
        : "r"(a[0]), "r"(a[1]), "r"(a[2]), "r"(a[3]), "r"(b[0]), "r"(b[1]));
}

// ---------------------------------------------------------------------------
// prep + lr fused. Blocks 0..383: h bf16 (4096 elems/block). 384..511: Wq/Wk
// bf16 (4096 elems/block). 512..895: lr.
// ---------------------------------------------------------------------------
__global__ void __launch_bounds__(256) prep_kernel(
    const float* __restrict__ h,
    const float* __restrict__ Wq,
    const float* __restrict__ Wk,
    const float* __restrict__ wlr, const float* __restrict__ blr,
    const float* __restrict__ wrl, const float* __restrict__ brl)
{
    const int blk = blockIdx.x;
    if (blk < 512) {
        const float* src;
        __nv_bfloat16* dst;
        long base;
        if (blk < 384)      { src = h;  dst = g_hh;  base = (long)blk * 4096; }
        else if (blk < 448) { src = Wq; dst = g_wqh; base = (long)(blk - 384) * 4096; }
        else                { src = Wk; dst = g_wkh; base = (long)(blk - 448) * 4096; }

        const long o = base + (long)threadIdx.x * 16;
#pragma unroll
        for (int half = 0; half < 2; half++) {
            const long oo = o + half * 8;
            float4 x0 = *(const float4*)(src + oo);
            float4 x1 = *(const float4*)(src + oo + 4);
            float v[8] = {x0.x, x0.y, x0.z, x0.w, x1.x, x1.y, x1.z, x1.w};
            __nv_bfloat162 p[4];
#pragma unroll
            for (int e = 0; e < 4; e++) {
                p[e].x = __float2bfloat16(v[e * 2]);
                p[e].y = __float2bfloat16(v[e * 2 + 1]);
            }
            *(uint4*)(dst + oo) = *(uint4*)p;
        }
    } else {
        const int row = (blk - 512) * 8 + (threadIdx.x >> 5);
        const int lane = threadIdx.x & 31;
        const float* hr = h + (size_t)row * DD;
        float sl = 0.f, sr = 0.f;
        for (int d = lane; d < DD; d += 32) {
            float hv = hr[d];
            sl = fmaf(hv, wlr[d], sl);
            sr = fmaf(hv, wrl[d], sr);
        }
#pragma unroll
        for (int o = 16; o; o >>= 1) {
            sl += __shfl_down_sync(0xFFFFFFFFu, sl, o);
            sr += __shfl_down_sync(0xFFFFFFFFu, sr, o);
        }
        if (lane == 0) {
            g_left[row]  = sl + blr[0];
            g_right[row] = sr + brl[0];
        }
    }
}

// ---------------------------------------------------------------------------
// Plain bf16 GEMM core: C += A * B^T.
// Tile M = MW*MF*16, N = NW*NF*8, K = 512 in 16 chunks of 32.
// Stage layout: A | B.
// ---------------------------------------------------------------------------
template<int MW, int NW, int MF, int NF, int STAGES>
__device__ __forceinline__ void gemm1(
    const __nv_bfloat16* __restrict__ A,
    const __nv_bfloat16* __restrict__ B,
    char* smem, float acc[MF][NF][4])
{
    constexpr int MT = MW * MF * 16;
    constexpr int NT = NW * NF * 8;
    constexpr int A_BYTES = MT * SMROW;
    constexpr int B_BYTES = NT * SMROW;
    constexpr int STAGE = A_BYTES + B_BYTES;
    constexpr int NTHR = MW * NW * 32;

    const int tid = threadIdx.x;
    const int wid = tid >> 5, lane = tid & 31;
    const int wm = wid % MW, wn = wid / MW;
    const uint32_t s0 = smem_u32(smem);

    const uint32_t a_off = (uint32_t)(lane & 15) * SMROW + (uint32_t)(lane >> 4) * 16;
    const uint32_t b_off = (uint32_t)((lane & 7) + ((lane >> 4) << 3)) * SMROW
                         + (uint32_t)((lane >> 3) & 1) * 16;

    auto issue = [&](int cc) {
        const int k0 = cc * 32;
        const uint32_t sb = s0 + (cc % STAGES) * STAGE;
#pragma unroll
        for (int idx = tid; idx < MT * 4; idx += NTHR) {
            const int r = idx >> 2, g = idx & 3;
            cp16(sb + (uint32_t)r * SMROW + g * 16,
                 A + (size_t)r * DD + k0 + g * 8);
        }
#pragma unroll
        for (int idx = tid; idx < NT * 4; idx += NTHR) {
            const int r = idx >> 2, g = idx & 3;
            cp16(sb + A_BYTES + (uint32_t)r * SMROW + g * 16,
                 B + (size_t)r * DD + k0 + g * 8);
        }
        CP_COMMIT();
    };

#pragma unroll
    for (int p = 0; p < STAGES - 1; p++) issue(p);

#pragma unroll 1
    for (int c = 0; c < 16; c++) {
        if (c + STAGES - 1 < 16) issue(c + STAGES - 1);

        const int rem = 15 - c;
        const int ahead = rem < (STAGES - 1) ? rem : (STAGES - 1);
        if      (ahead <= 0) asm volatile("cp.async.wait_group 0;" ::: "memory");
        else if (ahead == 1) asm volatile("cp.async.wait_group 1;" ::: "memory");
        else if (ahead == 2) asm volatile("cp.async.wait_group 2;" ::: "memory");
        else                 asm volatile("cp.async.wait_group 3;" ::: "memory");
        __syncthreads();

        const uint32_t sb = s0 + (c % STAGES) * STAGE;
#pragma unroll
        for (int ks = 0; ks < 2; ks++) {
            const uint32_t kb = ks * 32;
            uint32_t ahf[MF][4];
#pragma unroll
            for (int mf = 0; mf < MF; mf++) {
                const uint32_t rb = (uint32_t)(wm * MF * 16 + mf * 16) * SMROW + kb + a_off;
                ldsm4(ahf[mf], sb + rb);
            }
#pragma unroll
            for (int np = 0; np < NF / 2; np++) {
                const uint32_t nb = (uint32_t)(wn * NF * 8 + np * 16) * SMROW + kb + b_off;
                uint32_t bh[4];
                ldsm4(bh, sb + A_BYTES + nb);
#pragma unroll
                for (int mf = 0; mf < MF; mf++) {
                    mma16816(acc[mf][np * 2],     ahf[mf], bh);
                    mma16816(acc[mf][np * 2 + 1], ahf[mf], bh + 2);
                }
            }
        }
        __syncthreads();
    }
}

// ---------------------------------------------------------------------------
// proj: q = h Wq^T + bq (z=0), k = h Wk^T (z=1). bf16 stores.
// Tile 128x64 (MW=4, MF=2, NW=2, NF=4), 4-stage (stage 15360 B, 61440 total,
// 3 CTAs/SM). Grid (8, 24, 2) = 384 CTAs.
// ---------------------------------------------------------------------------
__global__ void __launch_bounds__(256) proj_kernel(const float* __restrict__ bq)
{
    extern __shared__ char smem[];
    const int n0 = blockIdx.x * 64;
    const int m0 = blockIdx.y * 128;
    const int z  = blockIdx.z;

    const __nv_bfloat16* B = (z ? g_wkh : g_wqh) + (size_t)n0 * DD;

    float acc[2][4][4];
#pragma unroll
    for (int a = 0; a < 2; a++)
#pragma unroll
        for (int f = 0; f < 4; f++)
#pragma unroll
            for (int e = 0; e < 4; e++) acc[a][f][e] = 0.f;

    gemm1<4, 2, 2, 4, 4>(g_hh + (size_t)m0 * DD, B, smem, acc);

    const int wid = threadIdx.x >> 5, lane = threadIdx.x & 31;
    const int wm = wid & 3, wn = wid >> 2;
    __nv_bfloat16* out = z ? g_kh : g_qh;

#pragma unroll
    for (int mf = 0; mf < 2; mf++) {
        const int r0 = m0 + wm * 32 + mf * 16 + (lane >> 2);
#pragma unroll
        for (int f = 0; f < 4; f++) {
            const int c = n0 + wn * 32 + f * 8 + (lane & 3) * 2;
            const float b0 = z ? 0.f : __ldg(&bq[c]);
            const float b1 = z ? 0.f : __ldg(&bq[c + 1]);
            __nv_bfloat162 p0, p1;
            p0.x = __float2bfloat16(acc[mf][f][0] + b0);
            p0.y = __float2bfloat16(acc[mf][f][1] + b1);
            p1.x = __float2bfloat16(acc[mf][f][2] + b0);
            p1.y = __float2bfloat16(acc[mf][f][3] + b1);
            *(__nv_bfloat162*)(out + (size_t)r0 * DD + c) = p0;
            *(__nv_bfloat162*)(out + (size_t)(r0 + 8) * DD + c) = p1;
        }
    }
}

// ---------------------------------------------------------------------------
// scores: per-batch S = q k^T, tile 64x64, 4-stage (stage 10240 B, 40960
// total, 4 CTAs/SM reg-limited). Grid (6,6,8) = 288 CTAs.
// Epilogue: raw = clip(alpha*S + beta*d + gamma) -> g_raw.
// ---------------------------------------------------------------------------
__global__ void __launch_bounds__(256) scores_kernel(
    const float* __restrict__ alpha_p,
    const float* __restrict__ beta_p,
    const float* __restrict__ gamma_p)
{
    extern __shared__ char smem[];
    const int b  = blockIdx.z;
    const int m0 = blockIdx.y * 64;
    const int n0 = blockIdx.x * 64;
    const size_t abase = ((size_t)b * NN + m0) * DD;
    const size_t bbase = ((size_t)b * NN + n0) * DD;

    float acc[2][2][4];
#pragma unroll
    for (int a = 0; a < 2; a++)
#pragma unroll
        for (int f = 0; f < 2; f++)
#pragma unroll
            for (int e = 0; e < 4; e++) acc[a][f][e] = 0.f;

    gemm1<2, 4, 2, 2, 4>(g_qh + abase, g_kh + bbase, smem, acc);

    const float alpha = alpha_p[0], beta = beta_p[0], gamma = gamma_p[0];
    const int wid = threadIdx.x >> 5, lane = threadIdx.x & 31;
    const int wm = wid & 1, wn = wid >> 1;

#pragma unroll
    for (int mf = 0; mf < 2; mf++) {
        const int rl = m0 + wm * 32 + mf * 16 + (lane >> 2);
#pragma unroll
        for (int rr = 0; rr < 2; rr++) {
            const int i = rl + rr * 8;
            const float lft = g_left[b * NN + i];
            const float rgt = g_right[b * NN + i];
            float* rb = g_raw + ((size_t)b * NN + i) * NN;
#pragma unroll
            for (int f = 0; f < 2; f++) {
                const int j = n0 + wn * 16 + f * 8 + (lane & 3) * 2;
                float2 o;
                {
                    const float dv = (j >= i) ? lft : rgt;
                    float raw = fmaf(alpha, acc[mf][f][rr * 2],
                                     fmaf(beta, dv, gamma));
                    o.x = fminf(fmaxf(raw, -16.f), 14.f);
                }
                {
                    const float dv = (j + 1 >= i) ? lft : rgt;
                    float raw = fmaf(alpha, acc[mf][f][rr * 2 + 1],
                                     fmaf(beta, dv, gamma));
                    o.y = fminf(fmaxf(raw, -16.f), 14.f);
                }
                *(float2*)(rb + j) = o;
            }
        }
    }
}

// ---------------------------------------------------------------------------
// finalize: warp-per-row, 4 rows per 128-thread block, 768 blocks.
// ---------------------------------------------------------------------------
__global__ void __launch_bounds__(128) finalize_kernel(
    const float* __restrict__ mask,
    float* __restrict__ r_out,
    float* __restrict__ am_out)
{
    const int wid = threadIdx.x >> 5;
    const int lane = threadIdx.x & 31;
    const int bi = blockIdx.x * 4 + wid;
    const int b = bi / NN;
    const int i = bi - b * NN;

    __shared__ float S[4][NN + 1];
    float* Srow = S[wid];

    const float* rawp = g_raw + (size_t)bi * NN + lane * 12;
    float raw[12];
    *(float4*)(raw + 0) = *(const float4*)(rawp + 0);
    *(float4*)(raw + 4) = *(const float4*)(rawp + 4);
    *(float4*)(raw + 8) = *(const float4*)(rawp + 8);

    float l1[12], pre[12];
    float run = 0.f;
#pragma unroll
    for (int e = 0; e < 12; e++) {
        l1[e] = -__logf(1.f + __expf(raw[e]));
        run += l1[e];
        pre[e] = run;
    }

    float x = run;
#pragma unroll
    for (int o = 1; o < 32; o <<= 1) {
        float y = __shfl_up_sync(0xFFFFFFFFu, x, o);
        if (lane >= o) x += y;
    }
    const float base = x - run;

    if (lane == 0) Srow[0] = 0.f;
#pragma unroll
    for (int e = 0; e < 12; e++)
        Srow[lane * 12 + e + 1] = base + pre[e];
    __syncwarp();

    const float mi = mask[b * NN + i];
    float mj[12];
    {
        const float* mp = mask + b * NN + lane * 12;
        *(float4*)(mj + 0) = *(const float4*)(mp + 0);
        *(float4*)(mj + 4) = *(const float4*)(mp + 4);
        *(float4*)(mj + 8) = *(const float4*)(mp + 8);
    }

    float r[12], am[12];
#pragma unroll
    for (int e = 0; e < 12; e++) {
        const int j = lane * 12 + e;
        const float lp = raw[e] + l1[e];
        float a;
        if (i == j) {
            a = lp - 10000.f;
        } else if (i < j) {
            const int lo = max(2 * i - j + 1, 0);
            a = lp + (Srow[j] - Srow[i + 1]) + (Srow[i] - Srow[lo]);
        } else {
            const int hi = min(2 * i - j, NN - 1);
            a = lp + (Srow[i] - Srow[j + 1]) + (Srow[hi + 1] - Srow[i + 1]);
        }
        r[e] = a;
        am[e] = mi * mj[e];
    }

    float* rp = r_out + (size_t)bi * NN + lane * 12;
    *(float4*)(rp + 0) = *(float4*)(r + 0);
    *(float4*)(rp + 4) = *(float4*)(r + 4);
    *(float4*)(rp + 8) = *(float4*)(r + 8);
    if (am_out) {
        float* ap = am_out + (size_t)bi * NN + lane * 12;
        *(float4*)(ap + 0) = *(float4*)(am + 0);
        *(float4*)(ap + 4) = *(float4*)(am + 4);
        *(float4*)(ap + 8) = *(float4*)(am + 8);
    }
}

// ---------------------------------------------------------------------------
// Launch
// ---------------------------------------------------------------------------
extern "C" void kernel_launch(void* const* d_in, const int* in_sizes, int n_in,
                              void* d_out, int out_size)
{
    const float* h     = (const float*)d_in[0];
    const float* mask  = (const float*)d_in[1];
    const float* Wq    = (const float*)d_in[2];
    const float* bq    = (const float*)d_in[3];
    const float* Wk    = (const float*)d_in[4];
    const float* wlr   = (const float*)d_in[5];
    const float* blr   = (const float*)d_in[6];
    const float* wrl   = (const float*)d_in[7];
    const float* brl   = (const float*)d_in[8];
    const float* alpha = (const float*)d_in[9];
    const float* beta  = (const float*)d_in[10];
    const float* gamma = (const float*)d_in[11];

    float* r_out = (float*)d_out;
    const long long BNN = (long long)BB * NN * NN;
    float* am_out = (out_size >= 2 * BNN) ? (r_out + BNN) : nullptr;

    // proj: stage (128 + 64)*80 = 15360 B * 4 = 61440 B (3 CTAs/SM)
    // scores: stage (64 + 64)*80 = 10240 B * 4 = 40960 B (4 CTAs/SM)
    static bool attr_set = false;
    const int proj_smem = 61440, scores_smem = 40960;
    if (!attr_set) {
        cudaFuncSetAttribute(proj_kernel,
                             cudaFuncAttributeMaxDynamicSharedMemorySize, proj_smem);
        cudaFuncSetAttribute(scores_kernel,
                             cudaFuncAttributeMaxDynamicSharedMemorySize, scores_smem);
        attr_set = true;
    }

    prep_kernel<<<896, 256>>>(h, Wq, Wk, wlr, blr, wrl, brl);
    proj_kernel<<<dim3(8, 24, 2), 256, proj_smem>>>(bq);
    scores_kernel<<<dim3(6, 6, 8), 256, scores_smem>>>(alpha, beta, gamma);
    finalize_kernel<<<768, 128>>>(mask, r_out, am_out);
}